// round 1
// baseline (speedup 1.0000x reference)
#include <cuda_runtime.h>
#include <cuda_bf16.h>
#include <math.h>

// Problem constants (DIM=1024, T=2048, B=16, N_GROUPS=32) — scratch sized for them,
// runtime dims derived from in_sizes.
#define MAX_TBD (2048*16*1024)          // T*B*D elements
#define MAX_HALL ((2048+1)*16*1024)     // (T+1)*B*D

__device__ float g_delta[MAX_TBD];
__device__ float g_cand[MAX_TBD];
__device__ float g_comp[MAX_TBD];
__device__ float g_hall[MAX_HALL];      // fallback only if d_out holds just `outs`

// ---------------------------------------------------------------------------
// NT SGEMM: C[M,N] = epilogue( A[M,K] @ B[N,K]^T )
// 128x128 block tile, BK=8, 256 threads, 8x8 per-thread microtile.
// MODE 0: sigmoid(acc + bias)          -> delta
// MODE 1: acc + bias                   -> cand
// MODE 2: comp[m,n] * silu(acc)        -> outs
// ---------------------------------------------------------------------------
template <int MODE>
__global__ void __launch_bounds__(256) gemm_nt_kernel(
    const float* __restrict__ A,
    const float* __restrict__ Bw,
    const float* __restrict__ bias,
    const float* __restrict__ comp,
    float* __restrict__ C,
    int M, int N, int K)
{
    const int BM = 128, BN = 128, BK = 8;
    __shared__ float As[BK][BM];
    __shared__ float Bs[BK][BN];

    const int tid = threadIdx.x;
    const int tx = tid & 15;          // 0..15 -> n microtile
    const int ty = tid >> 4;          // 0..15 -> m microtile
    const int rL = tid >> 1;          // load row within tile (0..127)
    const int cL = (tid & 1) * 4;     // load col within BK (0 or 4)

    const float* Ab = A + (size_t)blockIdx.y * BM * K;
    const float* Bb = Bw + (size_t)blockIdx.x * BN * K;

    float acc[8][8];
#pragma unroll
    for (int i = 0; i < 8; ++i)
#pragma unroll
        for (int j = 0; j < 8; ++j) acc[i][j] = 0.f;

    for (int k0 = 0; k0 < K; k0 += BK) {
        float4 av = *(const float4*)(Ab + (size_t)rL * K + k0 + cL);
        float4 bv = *(const float4*)(Bb + (size_t)rL * K + k0 + cL);
        __syncthreads();
        As[cL + 0][rL] = av.x; As[cL + 1][rL] = av.y;
        As[cL + 2][rL] = av.z; As[cL + 3][rL] = av.w;
        Bs[cL + 0][rL] = bv.x; Bs[cL + 1][rL] = bv.y;
        Bs[cL + 2][rL] = bv.z; Bs[cL + 3][rL] = bv.w;
        __syncthreads();
#pragma unroll
        for (int k = 0; k < BK; ++k) {
            float a[8], b[8];
            *(float4*)(a + 0) = *(const float4*)&As[k][ty * 8 + 0];
            *(float4*)(a + 4) = *(const float4*)&As[k][ty * 8 + 4];
            *(float4*)(b + 0) = *(const float4*)&Bs[k][tx * 8 + 0];
            *(float4*)(b + 4) = *(const float4*)&Bs[k][tx * 8 + 4];
#pragma unroll
            for (int i = 0; i < 8; ++i)
#pragma unroll
                for (int j = 0; j < 8; ++j)
                    acc[i][j] = fmaf(a[i], b[j], acc[i][j]);
        }
    }

    const int m0 = blockIdx.y * BM + ty * 8;
    const int n0 = blockIdx.x * BN + tx * 8;

    float bia[8];
    if (MODE == 0 || MODE == 1) {
#pragma unroll
        for (int j = 0; j < 8; ++j) bia[j] = bias[n0 + j];
    }

#pragma unroll
    for (int i = 0; i < 8; ++i) {
        size_t row = (size_t)(m0 + i) * N + n0;
        float v[8];
        if (MODE == 0) {
#pragma unroll
            for (int j = 0; j < 8; ++j) {
                float z = acc[i][j] + bia[j];
                v[j] = 1.f / (1.f + __expf(-z));
            }
        } else if (MODE == 1) {
#pragma unroll
            for (int j = 0; j < 8; ++j) v[j] = acc[i][j] + bia[j];
        } else {
            float cp[8];
            *(float4*)(cp + 0) = *(const float4*)(comp + row + 0);
            *(float4*)(cp + 4) = *(const float4*)(comp + row + 4);
#pragma unroll
            for (int j = 0; j < 8; ++j) {
                float y = acc[i][j];
                float s = y / (1.f + __expf(-y));   // silu
                v[j] = cp[j] * s;
            }
        }
        *(float4*)(C + row + 0) = *(float4*)(v + 0);
        *(float4*)(C + row + 4) = *(float4*)(v + 4);
    }
}

// ---------------------------------------------------------------------------
// Diagonal scan: 16384 independent lanes, each steps T times.
// Register double-buffered groups of 8 to cover DRAM latency at low occupancy.
// ---------------------------------------------------------------------------
__global__ void scan_kernel(const float* __restrict__ delta,
                            const float* __restrict__ cand,
                            const float* __restrict__ h0,
                            const float* __restrict__ r_h,
                            float* __restrict__ h_all,
                            int T, int BD, int D)
{
    int lane = blockIdx.x * blockDim.x + threadIdx.x;
    if (lane >= BD) return;

    float h = h0[lane];
    float rh = r_h[lane % D];
    h_all[lane] = h;                       // h_all[0] = h0

    const float* dp = delta + lane;
    const float* cp = cand + lane;
    float* hp = h_all + BD + lane;

    const int U = 8;
    int nG = T / U;
    float db[2][U], cb[2][U];

#pragma unroll
    for (int u = 0; u < U; ++u) {
        db[0][u] = dp[(size_t)u * BD];
        cb[0][u] = cp[(size_t)u * BD];
    }

    int buf = 0;
    for (int g = 0; g < nG; ++g) {
        int nb = buf ^ 1;
        if (g + 1 < nG) {
            size_t base = (size_t)(g + 1) * U * BD;
#pragma unroll
            for (int u = 0; u < U; ++u) {
                db[nb][u] = dp[base + (size_t)u * BD];
                cb[nb][u] = cp[base + (size_t)u * BD];
            }
        }
        size_t ob = (size_t)g * U * BD;
#pragma unroll
        for (int u = 0; u < U; ++u) {
            float d = db[buf][u], c = cb[buf][u];
            float cv = tanhf(fmaf(rh, h, c));
            h = fmaf(d, cv - h, h);        // (1-d)*h + d*cv
            hp[ob + (size_t)u * BD] = h;
        }
        buf = nb;
    }
    for (int t = nG * U; t < T; ++t) {     // generic remainder
        float d = dp[(size_t)t * BD], c = cp[(size_t)t * BD];
        float cv = tanhf(fmaf(rh, h, c));
        h = fmaf(d, cv - h, h);
        hp[(size_t)t * BD] = h;
    }
}

// ---------------------------------------------------------------------------
// Group softmax (group size 32 == warp): compete[t,b,g,:] = softmax(h[t,b,g,:])
// ---------------------------------------------------------------------------
__global__ void compete_kernel(const float* __restrict__ h,
                               float* __restrict__ comp,
                               size_t total)
{
    size_t i = (size_t)blockIdx.x * blockDim.x + threadIdx.x;
    if (i >= total) return;
    float v = h[i];
    float mx = v;
#pragma unroll
    for (int s = 16; s; s >>= 1)
        mx = fmaxf(mx, __shfl_xor_sync(0xffffffffu, mx, s));
    float e = __expf(v - mx);
    float sum = e;
#pragma unroll
    for (int s = 16; s; s >>= 1)
        sum += __shfl_xor_sync(0xffffffffu, sum, s);
    comp[i] = e / sum;
}

extern "C" void kernel_launch(void* const* d_in, const int* in_sizes, int n_in,
                              void* d_out, int out_size)
{
    const float* x       = (const float*)d_in[0];
    const float* h0      = (const float*)d_in[1];
    const float* W_x     = (const float*)d_in[2];
    const float* r_h     = (const float*)d_in[3];
    const float* b       = (const float*)d_in[4];
    const float* W_delta = (const float*)d_in[5];
    const float* b_delta = (const float*)d_in[6];
    const float* W_out   = (const float*)d_in[7];
    float* out = (float*)d_out;

    // Derive dims: W_x is [D,D], h0 is [B,D], x is [T,B,D]
    int D = (int)(sqrt((double)in_sizes[2]) + 0.5);
    int Bn = in_sizes[1] / D;
    int Tn = in_sizes[0] / (Bn * D);
    int BD = Bn * D;
    int M = Tn * Bn;

    float *gd, *gc, *gcomp, *ghall;
    cudaGetSymbolAddress((void**)&gd,    g_delta);
    cudaGetSymbolAddress((void**)&gc,    g_cand);
    cudaGetSymbolAddress((void**)&gcomp, g_comp);
    cudaGetSymbolAddress((void**)&ghall, g_hall);

    // Output layout: tuple (h_all, outs) flattened; fall back to outs-only.
    float* hall;
    float* outs;
    long need_both = (long)(Tn + 1) * BD + (long)M * D;
    if ((long)out_size >= need_both) {
        hall = out;
        outs = out + (size_t)(Tn + 1) * BD;
    } else {
        hall = ghall;
        outs = out;
    }

    dim3 ggrid(D / 128, M / 128);

    // Phase 1: gate & candidate GEMMs (parallel over T*B)
    gemm_nt_kernel<0><<<ggrid, 256>>>(x, W_delta, b_delta, nullptr, gd, M, D, D);
    gemm_nt_kernel<1><<<ggrid, 256>>>(x, W_x,     b,       nullptr, gc, M, D, D);

    // Phase 2: diagonal elementwise scan (only true sequential part)
    scan_kernel<<<(BD + 127) / 128, 128>>>(gd, gc, h0, r_h, hall, Tn, BD, D);

    // Phase 3: group softmax over h[1..T]
    size_t total = (size_t)M * D;
    compete_kernel<<<(unsigned)((total + 255) / 256), 256>>>(hall + BD, gcomp, total);

    // Phase 4: output GEMM + silu + compete gating
    gemm_nt_kernel<2><<<ggrid, 256>>>(hall + BD, W_out, nullptr, gcomp, outs, M, D, D);
}

// round 3
// speedup vs baseline: 2.0207x; 2.0207x over previous
#include <cuda_runtime.h>
#include <cuda_bf16.h>
#include <math.h>
#include <stdint.h>

// ---------------------------------------------------------------------------
// Scratch (no allocation allowed)
// ---------------------------------------------------------------------------
#define MAX_TBD (2048*16*1024)
#define MAX_HALL ((2048+1)*16*1024)
__device__ float g_delta[MAX_TBD];
__device__ float g_cand[MAX_TBD];
__device__ float g_hall[MAX_HALL];   // fallback if d_out holds only `outs`

// ---------------------------------------------------------------------------
// Helpers
// ---------------------------------------------------------------------------
__device__ __forceinline__ uint32_t smem_u32(const void* p) {
    uint32_t a;
    asm("{ .reg .u64 t; cvta.to.shared.u64 t, %1; cvt.u32.u64 %0, t; }" : "=r"(a) : "l"(p));
    return a;
}

#define LDSM_X4(r0, r1, r2, r3, addr) \
    asm volatile("ldmatrix.sync.aligned.m8n8.x4.shared.b16 {%0,%1,%2,%3}, [%4];" \
                 : "=r"(r0), "=r"(r1), "=r"(r2), "=r"(r3) : "r"(addr))

#define MMA16816(c, a, b0, b1) \
    asm volatile("mma.sync.aligned.m16n8k16.row.col.f32.bf16.bf16.f32 " \
                 "{%0,%1,%2,%3},{%4,%5,%6,%7},{%8,%9},{%0,%1,%2,%3};" \
                 : "+f"((c)[0]), "+f"((c)[1]), "+f"((c)[2]), "+f"((c)[3]) \
                 : "r"((a)[0]), "r"((a)[1]), "r"((a)[2]), "r"((a)[3]), \
                   "r"(b0), "r"(b1))

// split float4 -> 4 bf16 hi (truncate) + 4 bf16 lo (residual, rounded)
__device__ __forceinline__ void split4(const float4& f, uint2& hi, uint2& lo) {
    uint32_t x0 = __float_as_uint(f.x), x1 = __float_as_uint(f.y),
             x2 = __float_as_uint(f.z), x3 = __float_as_uint(f.w);
    hi.x = __byte_perm(x0, x1, 0x7632);
    hi.y = __byte_perm(x2, x3, 0x7632);
    float l0 = f.x - __uint_as_float(x0 & 0xFFFF0000u);
    float l1 = f.y - __uint_as_float(x1 & 0xFFFF0000u);
    float l2 = f.z - __uint_as_float(x2 & 0xFFFF0000u);
    float l3 = f.w - __uint_as_float(x3 & 0xFFFF0000u);
    asm("cvt.rn.bf16x2.f32 %0, %1, %2;" : "=r"(lo.x) : "f"(l1), "f"(l0));
    asm("cvt.rn.bf16x2.f32 %0, %1, %2;" : "=r"(lo.y) : "f"(l3), "f"(l2));
}

// ---------------------------------------------------------------------------
// HMMA GEMM: C = epi(A[M,K] @ B[N,K]^T), fp32 in/out, bf16 3-pass internally.
// BM=BN=128, BK=32, 256 threads (8 warps, 2x4 of 64x32 warp tiles),
// double-buffered smem, padded rows (32+8 bf16 = 80B) for conflict-free LDSM.
// MODE 0 (fused gate GEMM, grid.x = 2*D/128):
//   first half  -> W0=W_delta, sigmoid(acc+bias0) -> out0 (delta)
//   second half -> W1=W_x,             acc+bias1  -> out1 (cand)
// MODE 1 (output GEMM): compete(hsrc) * silu(acc) -> out0
//   compete = softmax over the warp's 32-col group (quad-lane shfl reduce)
// ---------------------------------------------------------------------------
#define STAGE_BYTES 40960     // 4 arrays (Ahi,Alo,Bhi,Blo) x 128 rows x 80B
#define GSMEM (2 * STAGE_BYTES)

template <int MODE>
__global__ void __launch_bounds__(256) gemm_tc(
    const float* __restrict__ A,
    const float* __restrict__ W0,
    const float* __restrict__ W1,
    const float* __restrict__ bias0,
    const float* __restrict__ bias1,
    float* __restrict__ out0,
    float* __restrict__ out1,
    const float* __restrict__ hsrc,
    int K, int ldC)
{
    extern __shared__ __align__(1024) char smem[];
    const uint32_t sb = smem_u32(smem);
    const int tid = threadIdx.x;
    const int wid = tid >> 5, lid = tid & 31;
    const int m0 = blockIdx.y * 128;

    const float* Bw;
    const float* bias = nullptr;
    float* Cout;
    int ncol0, sel = 0;
    if (MODE == 0) {
        int halfg = gridDim.x >> 1;
        sel = (blockIdx.x >= halfg);
        int nbl = sel ? blockIdx.x - halfg : blockIdx.x;
        Bw = (sel ? W1 : W0) + (size_t)nbl * 128 * K;
        bias = sel ? bias1 : bias0;
        Cout = sel ? out1 : out0;
        ncol0 = nbl * 128;
    } else {
        Bw = W0 + (size_t)blockIdx.x * 128 * K;
        Cout = out0;
        ncol0 = blockIdx.x * 128;
    }

    // global load mapping: thread -> row tid/2, k-halftile (tid&1)*16
    const int lr = tid >> 1, lc = (tid & 1) * 16;
    const float* Ap = A  + (size_t)(m0 + lr) * K + lc;
    const float* Bp = Bw + (size_t)lr * K + lc;
    const uint32_t sts_off = (uint32_t)lr * 80 + (uint32_t)lc * 2;

    const int wm = wid >> 2, wn = wid & 3;
    // ldmatrix lane-offset precompute (byte offsets within one operand array)
    const uint32_t aoff = ((uint32_t)((lid & 7) + ((lid >> 3) & 1) * 8) + (uint32_t)wm * 64) * 80
                        + (uint32_t)(lid >> 4) * 16;
    const uint32_t boff = ((uint32_t)((lid & 7) + (lid >> 4) * 8) + (uint32_t)wn * 32) * 80
                        + (uint32_t)((lid >> 3) & 1) * 16;

    float acc[4][4][4];
#pragma unroll
    for (int i = 0; i < 4; ++i)
#pragma unroll
        for (int j = 0; j < 4; ++j)
#pragma unroll
            for (int q = 0; q < 4; ++q) acc[i][j][q] = 0.f;

    const int NCH = K / 32;
    float4 av[4], bv[4];

    // prologue: chunk 0 -> stage 0
#pragma unroll
    for (int j = 0; j < 4; ++j) {
        av[j] = *(const float4*)(Ap + j * 4);
        bv[j] = *(const float4*)(Bp + j * 4);
    }
    {
        char* st = smem;
#pragma unroll
        for (int j = 0; j < 4; ++j) {
            uint2 hi, lo;
            split4(av[j], hi, lo);
            *(uint2*)(st + sts_off + j * 8)          = hi;
            *(uint2*)(st + 10240 + sts_off + j * 8)  = lo;
            split4(bv[j], hi, lo);
            *(uint2*)(st + 20480 + sts_off + j * 8)  = hi;
            *(uint2*)(st + 30720 + sts_off + j * 8)  = lo;
        }
    }
    __syncthreads();

    for (int ch = 0; ch < NCH; ++ch) {
        const int s = ch & 1;
        if (ch + 1 < NCH) {
            const size_t koff = (size_t)(ch + 1) * 32;
#pragma unroll
            for (int j = 0; j < 4; ++j) {
                av[j] = *(const float4*)(Ap + koff + j * 4);
                bv[j] = *(const float4*)(Bp + koff + j * 4);
            }
        }
        const uint32_t stA = sb + (uint32_t)s * STAGE_BYTES;
#pragma unroll
        for (int kk = 0; kk < 2; ++kk) {
            uint32_t bhi[4][2], blo[4][2];
#pragma unroll
            for (int p = 0; p < 2; ++p) {
                LDSM_X4(bhi[2*p][0], bhi[2*p][1], bhi[2*p+1][0], bhi[2*p+1][1],
                        stA + 20480 + boff + (uint32_t)p * 16 * 80 + (uint32_t)kk * 32);
                LDSM_X4(blo[2*p][0], blo[2*p][1], blo[2*p+1][0], blo[2*p+1][1],
                        stA + 30720 + boff + (uint32_t)p * 16 * 80 + (uint32_t)kk * 32);
            }
#pragma unroll
            for (int mi = 0; mi < 4; ++mi) {
                uint32_t ah[4], al[4];
                LDSM_X4(ah[0], ah[1], ah[2], ah[3],
                        stA + aoff + (uint32_t)mi * 16 * 80 + (uint32_t)kk * 32);
#pragma unroll
                for (int nj = 0; nj < 4; ++nj) MMA16816(acc[mi][nj], ah, bhi[nj][0], bhi[nj][1]);
#pragma unroll
                for (int nj = 0; nj < 4; ++nj) MMA16816(acc[mi][nj], ah, blo[nj][0], blo[nj][1]);
                LDSM_X4(al[0], al[1], al[2], al[3],
                        stA + 10240 + aoff + (uint32_t)mi * 16 * 80 + (uint32_t)kk * 32);
#pragma unroll
                for (int nj = 0; nj < 4; ++nj) MMA16816(acc[mi][nj], al, bhi[nj][0], bhi[nj][1]);
            }
        }
        if (ch + 1 < NCH) {
            char* st = smem + (size_t)((ch + 1) & 1) * STAGE_BYTES;
#pragma unroll
            for (int j = 0; j < 4; ++j) {
                uint2 hi, lo;
                split4(av[j], hi, lo);
                *(uint2*)(st + sts_off + j * 8)          = hi;
                *(uint2*)(st + 10240 + sts_off + j * 8)  = lo;
                split4(bv[j], hi, lo);
                *(uint2*)(st + 20480 + sts_off + j * 8)  = hi;
                *(uint2*)(st + 30720 + sts_off + j * 8)  = lo;
            }
        }
        __syncthreads();
    }

    // ---- epilogue ----
    const int rowW = m0 + wm * 64;
    const int colW = ncol0 + wn * 32;
    const int qr = lid >> 2;          // 0..7
    const int qc = 2 * (lid & 3);     // 0,2,4,6

    if (MODE == 0) {
        float2 bv2[4];
#pragma unroll
        for (int nj = 0; nj < 4; ++nj)
            bv2[nj] = *(const float2*)(bias + colW + nj * 8 + qc);
#pragma unroll
        for (int mi = 0; mi < 4; ++mi) {
            const int r0 = rowW + mi * 16 + qr;
#pragma unroll
            for (int nj = 0; nj < 4; ++nj) {
                const int c = colW + nj * 8 + qc;
                float v0 = acc[mi][nj][0] + bv2[nj].x;
                float v1 = acc[mi][nj][1] + bv2[nj].y;
                float v2 = acc[mi][nj][2] + bv2[nj].x;
                float v3 = acc[mi][nj][3] + bv2[nj].y;
                if (!sel) {
                    v0 = 1.f / (1.f + __expf(-v0));
                    v1 = 1.f / (1.f + __expf(-v1));
                    v2 = 1.f / (1.f + __expf(-v2));
                    v3 = 1.f / (1.f + __expf(-v3));
                }
                *(float2*)(Cout + (size_t)r0 * ldC + c)       = make_float2(v0, v1);
                *(float2*)(Cout + (size_t)(r0 + 8) * ldC + c) = make_float2(v2, v3);
            }
        }
    } else {
#pragma unroll
        for (int mi = 0; mi < 4; ++mi) {
            const int r0 = rowW + mi * 16 + qr;
            const int r1 = r0 + 8;
            float h0v[8], h1v[8];
#pragma unroll
            for (int nj = 0; nj < 4; ++nj) {
                float2 t0 = *(const float2*)(hsrc + (size_t)r0 * ldC + colW + nj * 8 + qc);
                float2 t1 = *(const float2*)(hsrc + (size_t)r1 * ldC + colW + nj * 8 + qc);
                h0v[2 * nj] = t0.x; h0v[2 * nj + 1] = t0.y;
                h1v[2 * nj] = t1.x; h1v[2 * nj + 1] = t1.y;
            }
            float mx0 = h0v[0], mx1 = h1v[0];
#pragma unroll
            for (int k = 1; k < 8; ++k) {
                mx0 = fmaxf(mx0, h0v[k]);
                mx1 = fmaxf(mx1, h1v[k]);
            }
            mx0 = fmaxf(mx0, __shfl_xor_sync(0xffffffffu, mx0, 1));
            mx0 = fmaxf(mx0, __shfl_xor_sync(0xffffffffu, mx0, 2));
            mx1 = fmaxf(mx1, __shfl_xor_sync(0xffffffffu, mx1, 1));
            mx1 = fmaxf(mx1, __shfl_xor_sync(0xffffffffu, mx1, 2));
            float s0 = 0.f, s1 = 0.f;
#pragma unroll
            for (int k = 0; k < 8; ++k) {
                h0v[k] = __expf(h0v[k] - mx0); s0 += h0v[k];
                h1v[k] = __expf(h1v[k] - mx1); s1 += h1v[k];
            }
            s0 += __shfl_xor_sync(0xffffffffu, s0, 1);
            s0 += __shfl_xor_sync(0xffffffffu, s0, 2);
            s1 += __shfl_xor_sync(0xffffffffu, s1, 1);
            s1 += __shfl_xor_sync(0xffffffffu, s1, 2);
            const float inv0 = 1.f / s0, inv1 = 1.f / s1;
#pragma unroll
            for (int nj = 0; nj < 4; ++nj) {
                const int c = colW + nj * 8 + qc;
                float y0 = acc[mi][nj][0], y1 = acc[mi][nj][1];
                float y2 = acc[mi][nj][2], y3 = acc[mi][nj][3];
                float v0 = (h0v[2 * nj]     * inv0) * (y0 / (1.f + __expf(-y0)));
                float v1 = (h0v[2 * nj + 1] * inv0) * (y1 / (1.f + __expf(-y1)));
                float v2 = (h1v[2 * nj]     * inv1) * (y2 / (1.f + __expf(-y2)));
                float v3 = (h1v[2 * nj + 1] * inv1) * (y3 / (1.f + __expf(-y3)));
                *(float2*)(Cout + (size_t)r0 * ldC + c) = make_float2(v0, v1);
                *(float2*)(Cout + (size_t)r1 * ldC + c) = make_float2(v2, v3);
            }
        }
    }
}

// ---------------------------------------------------------------------------
// Diagonal scan: 16384 independent lanes, register double-buffered
// ---------------------------------------------------------------------------
__global__ void scan_kernel(const float* __restrict__ delta,
                            const float* __restrict__ cand,
                            const float* __restrict__ h0,
                            const float* __restrict__ r_h,
                            float* __restrict__ h_all,
                            int T, int BD, int D)
{
    int lane = blockIdx.x * blockDim.x + threadIdx.x;
    if (lane >= BD) return;

    float h = h0[lane];
    float rh = r_h[lane % D];
    h_all[lane] = h;

    const float* dp = delta + lane;
    const float* cp = cand + lane;
    float* hp = h_all + BD + lane;

    const int U = 8;
    int nG = T / U;
    float db[2][U], cb[2][U];
#pragma unroll
    for (int u = 0; u < U; ++u) {
        db[0][u] = dp[(size_t)u * BD];
        cb[0][u] = cp[(size_t)u * BD];
    }
    int buf = 0;
    for (int g = 0; g < nG; ++g) {
        int nbuf = buf ^ 1;
        if (g + 1 < nG) {
            size_t base = (size_t)(g + 1) * U * BD;
#pragma unroll
            for (int u = 0; u < U; ++u) {
                db[nbuf][u] = dp[base + (size_t)u * BD];
                cb[nbuf][u] = cp[base + (size_t)u * BD];
            }
        }
        size_t ob = (size_t)g * U * BD;
#pragma unroll
        for (int u = 0; u < U; ++u) {
            float d = db[buf][u], c = cb[buf][u];
            float cv = tanhf(fmaf(rh, h, c));
            h = fmaf(d, cv - h, h);
            hp[ob + (size_t)u * BD] = h;
        }
        buf = nbuf;
    }
    for (int t = nG * U; t < T; ++t) {
        float d = dp[(size_t)t * BD], c = cp[(size_t)t * BD];
        float cv = tanhf(fmaf(rh, h, c));
        h = fmaf(d, cv - h, h);
        hp[(size_t)t * BD] = h;
    }
}

// ---------------------------------------------------------------------------
extern "C" void kernel_launch(void* const* d_in, const int* in_sizes, int n_in,
                              void* d_out, int out_size)
{
    const float* x       = (const float*)d_in[0];
    const float* h0      = (const float*)d_in[1];
    const float* W_x     = (const float*)d_in[2];
    const float* r_h     = (const float*)d_in[3];
    const float* b       = (const float*)d_in[4];
    const float* W_delta = (const float*)d_in[5];
    const float* b_delta = (const float*)d_in[6];
    const float* W_out   = (const float*)d_in[7];
    float* out = (float*)d_out;

    int D  = (int)(sqrt((double)in_sizes[2]) + 0.5);
    int Bn = in_sizes[1] / D;
    int Tn = in_sizes[0] / (Bn * D);
    int BD = Bn * D;
    int M  = Tn * Bn;

    float *gd, *gc, *ghall;
    cudaGetSymbolAddress((void**)&gd,    g_delta);
    cudaGetSymbolAddress((void**)&gc,    g_cand);
    cudaGetSymbolAddress((void**)&ghall, g_hall);

    float *hall, *outs;
    long need_both = (long)(Tn + 1) * BD + (long)M * D;
    if ((long)out_size >= need_both) {
        hall = out;
        outs = out + (size_t)(Tn + 1) * BD;
    } else {
        hall = ghall;
        outs = out;
    }

    cudaFuncSetAttribute(gemm_tc<0>, cudaFuncAttributeMaxDynamicSharedMemorySize, GSMEM);
    cudaFuncSetAttribute(gemm_tc<1>, cudaFuncAttributeMaxDynamicSharedMemorySize, GSMEM);

    // Phase 1: fused delta|cand GEMM (N = 2D)
    gemm_tc<0><<<dim3(2 * (D / 128), M / 128), 256, GSMEM>>>(
        x, W_delta, W_x, b_delta, b, gd, gc, nullptr, D, D);

    // Phase 2: diagonal scan
    scan_kernel<<<(BD + 127) / 128, 128>>>(gd, gc, h0, r_h, hall, Tn, BD, D);

    // Phase 3: output GEMM with fused compete-softmax + silu epilogue
    gemm_tc<1><<<dim3(D / 128, M / 128), 256, GSMEM>>>(
        hall + BD, W_out, nullptr, nullptr, nullptr, outs, nullptr, hall + BD, D, D);
}

// round 4
// speedup vs baseline: 2.0251x; 1.0022x over previous
#include <cuda_runtime.h>
#include <cuda_bf16.h>
#include <math.h>
#include <stdint.h>

// ---------------------------------------------------------------------------
// Scratch (no allocation allowed)
// ---------------------------------------------------------------------------
#define MAX_TBD (2048*16*1024)
#define MAX_HALL ((2048+1)*16*1024)
__device__ float g_delta[MAX_TBD];
__device__ float g_cand[MAX_TBD];
__device__ float g_hall[MAX_HALL];            // fallback if d_out holds only outs
__device__ unsigned short g_xs_hi[MAX_TBD];   // x split
__device__ unsigned short g_xs_lo[MAX_TBD];
__device__ unsigned short g_h_hi[MAX_TBD];    // h[1..T] split (written by scan)
__device__ unsigned short g_h_lo[MAX_TBD];
__device__ unsigned short g_w01_hi[2*1024*1024];  // [W_delta ; W_x]
__device__ unsigned short g_w01_lo[2*1024*1024];
__device__ unsigned short g_wo_hi[1024*1024];
__device__ unsigned short g_wo_lo[1024*1024];

// ---------------------------------------------------------------------------
// Helpers
// ---------------------------------------------------------------------------
__device__ __forceinline__ uint32_t smem_u32(const void* p) {
    uint32_t a;
    asm("{ .reg .u64 t; cvta.to.shared.u64 t, %1; cvt.u32.u64 %0, t; }" : "=r"(a) : "l"(p));
    return a;
}

#define LDSM_X4(r0, r1, r2, r3, addr) \
    asm volatile("ldmatrix.sync.aligned.m8n8.x4.shared.b16 {%0,%1,%2,%3}, [%4];" \
                 : "=r"(r0), "=r"(r1), "=r"(r2), "=r"(r3) : "r"(addr))

#define MMA16816(c, a, b0, b1) \
    asm volatile("mma.sync.aligned.m16n8k16.row.col.f32.bf16.bf16.f32 " \
                 "{%0,%1,%2,%3},{%4,%5,%6,%7},{%8,%9},{%0,%1,%2,%3};" \
                 : "+f"((c)[0]), "+f"((c)[1]), "+f"((c)[2]), "+f"((c)[3]) \
                 : "r"((a)[0]), "r"((a)[1]), "r"((a)[2]), "r"((a)[3]), \
                   "r"(b0), "r"(b1))

#define CP16(dst, src) \
    asm volatile("cp.async.cg.shared.global [%0], [%1], 16;" :: "r"(dst), "l"(src) : "memory")
#define CP_COMMIT() asm volatile("cp.async.commit_group;" ::: "memory")
#define CP_WAIT1()  asm volatile("cp.async.wait_group 1;" ::: "memory")
#define CP_WAIT0()  asm volatile("cp.async.wait_group 0;" ::: "memory")

// ---------------------------------------------------------------------------
// fp32 -> bf16 hi (truncate) + bf16 lo (residual, rounded), vectorized x4
// ---------------------------------------------------------------------------
__global__ void split_kernel(const float* __restrict__ src,
                             unsigned short* __restrict__ hi,
                             unsigned short* __restrict__ lo, int n4)
{
    int i = blockIdx.x * blockDim.x + threadIdx.x;
    if (i >= n4) return;
    float4 f = ((const float4*)src)[i];
    uint32_t b0 = __float_as_uint(f.x), b1 = __float_as_uint(f.y),
             b2 = __float_as_uint(f.z), b3 = __float_as_uint(f.w);
    ushort4 h;
    h.x = (unsigned short)(b0 >> 16); h.y = (unsigned short)(b1 >> 16);
    h.z = (unsigned short)(b2 >> 16); h.w = (unsigned short)(b3 >> 16);
    float l0 = f.x - __uint_as_float(b0 & 0xFFFF0000u);
    float l1 = f.y - __uint_as_float(b1 & 0xFFFF0000u);
    float l2 = f.z - __uint_as_float(b2 & 0xFFFF0000u);
    float l3 = f.w - __uint_as_float(b3 & 0xFFFF0000u);
    uint32_t p0, p1;
    asm("cvt.rn.bf16x2.f32 %0, %1, %2;" : "=r"(p0) : "f"(l1), "f"(l0));
    asm("cvt.rn.bf16x2.f32 %0, %1, %2;" : "=r"(p1) : "f"(l3), "f"(l2));
    ushort4 l;
    l.x = (unsigned short)(p0 & 0xffff); l.y = (unsigned short)(p0 >> 16);
    l.z = (unsigned short)(p1 & 0xffff); l.w = (unsigned short)(p1 >> 16);
    ((ushort4*)hi)[i] = h;
    ((ushort4*)lo)[i] = l;
}

// ---------------------------------------------------------------------------
// HMMA GEMM: C = epi(A[M,K] @ B[N,K]^T), bf16 hi/lo inputs (pre-split),
// 3-pass (hi*hi + hi*lo + lo*hi), fp32 accum.
// CTA tile 128(M) x 256(N), 8 warps (2x4), warp tile 64x64, BK=32.
// cp.async 2-stage pipeline, padded smem rows (32 bf16 + 8 pad = 80B).
// MODE 0: fused gate GEMM (N = 2D): first half sigmoid(acc+bias0)->out0,
//         second half acc+bias1 -> out1
// MODE 1: compete(hsrc) * silu(acc) -> out0 (softmax per 32-col group)
// ---------------------------------------------------------------------------
#define STG_A_LO 10240
#define STG_B_HI 20480
#define STG_B_LO 40960
#define STAGE_SZ 61440
#define GSMEM (2 * STAGE_SZ)

template <int MODE>
__global__ void __launch_bounds__(256) gemm_tc(
    const unsigned short* __restrict__ Ahi,
    const unsigned short* __restrict__ Alo,
    const unsigned short* __restrict__ Bhi,
    const unsigned short* __restrict__ Blo,
    const float* __restrict__ bias0,
    const float* __restrict__ bias1,
    float* __restrict__ out0,
    float* __restrict__ out1,
    const float* __restrict__ hsrc,
    int K, int ldC)
{
    extern __shared__ __align__(1024) char smem[];
    const uint32_t sb = smem_u32(smem);
    const int tid = threadIdx.x, wid = tid >> 5, lid = tid & 31;
    const int m0 = blockIdx.y * 128;
    const int n0 = blockIdx.x * 256;

    // cp.async per-thread mapping
    const size_t aRow = (size_t)(m0 + (tid >> 1)) * K + (size_t)(tid & 1) * 16;
    const uint32_t aDst = (uint32_t)(tid >> 1) * 80 + (uint32_t)(tid & 1) * 32;
    const size_t bRow = (size_t)(n0 + tid) * K;
    const uint32_t bDst = (uint32_t)tid * 80;

    const int wm = wid >> 2, wn = wid & 3;
    const uint32_t aoff = ((uint32_t)((lid & 7) + ((lid >> 3) & 1) * 8) + (uint32_t)wm * 64) * 80
                        + (uint32_t)(lid >> 4) * 16;
    const uint32_t boff = ((uint32_t)((lid & 7) + (lid >> 4) * 8) + (uint32_t)wn * 64) * 80
                        + (uint32_t)((lid >> 3) & 1) * 16;

    float acc[4][8][4];
#pragma unroll
    for (int i = 0; i < 4; ++i)
#pragma unroll
        for (int j = 0; j < 8; ++j)
#pragma unroll
            for (int q = 0; q < 4; ++q) acc[i][j][q] = 0.f;

    const int NCH = K / 32;

    auto issue = [&](int ch, int s) {
        const uint32_t stb = sb + (uint32_t)s * STAGE_SZ;
        const size_t ko = (size_t)ch * 32;
        const unsigned short* ga  = Ahi + aRow + ko;
        const unsigned short* gal = Alo + aRow + ko;
        uint32_t d = stb + aDst;
        CP16(d,                 ga);
        CP16(d + 16,            ga + 8);
        CP16(d + STG_A_LO,      gal);
        CP16(d + STG_A_LO + 16, gal + 8);
        const unsigned short* gb  = Bhi + bRow + ko;
        const unsigned short* gbl = Blo + bRow + ko;
        uint32_t db = stb + STG_B_HI + bDst;
#pragma unroll
        for (int p = 0; p < 4; ++p) {
            CP16(db + p * 16,         gb  + p * 8);
            CP16(db + 20480 + p * 16, gbl + p * 8);
        }
    };

    issue(0, 0);
    CP_COMMIT();

#pragma unroll 1
    for (int ch = 0; ch < NCH; ++ch) {
        const int s = ch & 1;
        if (ch + 1 < NCH) { issue(ch + 1, s ^ 1); CP_COMMIT(); CP_WAIT1(); }
        else              { CP_WAIT0(); }
        __syncthreads();

        const uint32_t stA = sb + (uint32_t)s * STAGE_SZ;
#pragma unroll
        for (int kk = 0; kk < 2; ++kk) {
            const uint32_t kof = (uint32_t)kk * 32;
            uint32_t bh[8][2], bl[8][2];
#pragma unroll
            for (int p = 0; p < 4; ++p) {
                LDSM_X4(bh[2*p][0], bh[2*p][1], bh[2*p+1][0], bh[2*p+1][1],
                        stA + STG_B_HI + boff + (uint32_t)p * 1280 + kof);
                LDSM_X4(bl[2*p][0], bl[2*p][1], bl[2*p+1][0], bl[2*p+1][1],
                        stA + STG_B_LO + boff + (uint32_t)p * 1280 + kof);
            }
#pragma unroll
            for (int mi = 0; mi < 4; ++mi) {
                uint32_t ah[4], al[4];
                LDSM_X4(ah[0], ah[1], ah[2], ah[3],
                        stA + aoff + (uint32_t)mi * 1280 + kof);
#pragma unroll
                for (int nj = 0; nj < 8; ++nj) MMA16816(acc[mi][nj], ah, bh[nj][0], bh[nj][1]);
#pragma unroll
                for (int nj = 0; nj < 8; ++nj) MMA16816(acc[mi][nj], ah, bl[nj][0], bl[nj][1]);
                LDSM_X4(al[0], al[1], al[2], al[3],
                        stA + STG_A_LO + aoff + (uint32_t)mi * 1280 + kof);
#pragma unroll
                for (int nj = 0; nj < 8; ++nj) MMA16816(acc[mi][nj], al, bh[nj][0], bh[nj][1]);
            }
        }
        __syncthreads();
    }

    // ---- epilogue ----
    const int qr = lid >> 2;       // 0..7
    const int qc = 2 * (lid & 3);  // 0,2,4,6

    if (MODE == 0) {
        const int halfN = gridDim.x * 128;   // N/2
        const int sel = (n0 >= halfN);
        const float* bias = sel ? bias1 : bias0;
        float* Cout = sel ? out1 : out0;
        const int colBase = (n0 - sel * halfN) + wn * 64;
        float2 bv2[8];
#pragma unroll
        for (int nj = 0; nj < 8; ++nj)
            bv2[nj] = *(const float2*)(bias + colBase + nj * 8 + qc);
#pragma unroll
        for (int mi = 0; mi < 4; ++mi) {
            const int r0 = m0 + wm * 64 + mi * 16 + qr;
#pragma unroll
            for (int nj = 0; nj < 8; ++nj) {
                const int c = colBase + nj * 8 + qc;
                float v0 = acc[mi][nj][0] + bv2[nj].x;
                float v1 = acc[mi][nj][1] + bv2[nj].y;
                float v2 = acc[mi][nj][2] + bv2[nj].x;
                float v3 = acc[mi][nj][3] + bv2[nj].y;
                if (!sel) {
                    v0 = 1.f / (1.f + __expf(-v0));
                    v1 = 1.f / (1.f + __expf(-v1));
                    v2 = 1.f / (1.f + __expf(-v2));
                    v3 = 1.f / (1.f + __expf(-v3));
                }
                *(float2*)(Cout + (size_t)r0 * ldC + c)       = make_float2(v0, v1);
                *(float2*)(Cout + (size_t)(r0 + 8) * ldC + c) = make_float2(v2, v3);
            }
        }
    } else {
        const int colBase = n0 + wn * 64;
#pragma unroll
        for (int mi = 0; mi < 4; ++mi) {
            const int r0 = m0 + wm * 64 + mi * 16 + qr;
            const int r1 = r0 + 8;
#pragma unroll
            for (int g = 0; g < 2; ++g) {
                float h0v[8], h1v[8];
#pragma unroll
                for (int j = 0; j < 4; ++j) {
                    const int c = colBase + g * 32 + j * 8 + qc;
                    float2 t0 = *(const float2*)(hsrc + (size_t)r0 * ldC + c);
                    float2 t1 = *(const float2*)(hsrc + (size_t)r1 * ldC + c);
                    h0v[2*j] = t0.x; h0v[2*j+1] = t0.y;
                    h1v[2*j] = t1.x; h1v[2*j+1] = t1.y;
                }
                float mx0 = h0v[0], mx1 = h1v[0];
#pragma unroll
                for (int k = 1; k < 8; ++k) {
                    mx0 = fmaxf(mx0, h0v[k]);
                    mx1 = fmaxf(mx1, h1v[k]);
                }
                mx0 = fmaxf(mx0, __shfl_xor_sync(0xffffffffu, mx0, 1));
                mx0 = fmaxf(mx0, __shfl_xor_sync(0xffffffffu, mx0, 2));
                mx1 = fmaxf(mx1, __shfl_xor_sync(0xffffffffu, mx1, 1));
                mx1 = fmaxf(mx1, __shfl_xor_sync(0xffffffffu, mx1, 2));
                float s0 = 0.f, s1 = 0.f;
#pragma unroll
                for (int k = 0; k < 8; ++k) {
                    h0v[k] = __expf(h0v[k] - mx0); s0 += h0v[k];
                    h1v[k] = __expf(h1v[k] - mx1); s1 += h1v[k];
                }
                s0 += __shfl_xor_sync(0xffffffffu, s0, 1);
                s0 += __shfl_xor_sync(0xffffffffu, s0, 2);
                s1 += __shfl_xor_sync(0xffffffffu, s1, 1);
                s1 += __shfl_xor_sync(0xffffffffu, s1, 2);
                const float inv0 = 1.f / s0, inv1 = 1.f / s1;
#pragma unroll
                for (int j = 0; j < 4; ++j) {
                    const int nj = g * 4 + j;
                    const int c = colBase + g * 32 + j * 8 + qc;
                    float y0 = acc[mi][nj][0], y1 = acc[mi][nj][1];
                    float y2 = acc[mi][nj][2], y3 = acc[mi][nj][3];
                    float v0 = (h0v[2*j]   * inv0) * (y0 / (1.f + __expf(-y0)));
                    float v1 = (h0v[2*j+1] * inv0) * (y1 / (1.f + __expf(-y1)));
                    float v2 = (h1v[2*j]   * inv1) * (y2 / (1.f + __expf(-y2)));
                    float v3 = (h1v[2*j+1] * inv1) * (y3 / (1.f + __expf(-y3)));
                    *(float2*)(out0 + (size_t)r0 * ldC + c) = make_float2(v0, v1);
                    *(float2*)(out0 + (size_t)r1 * ldC + c) = make_float2(v2, v3);
                }
            }
        }
    }
}

// ---------------------------------------------------------------------------
// Diagonal scan: also emits bf16 hi/lo split of h[1..T] for the out-GEMM.
// ---------------------------------------------------------------------------
__global__ void scan_kernel(const float* __restrict__ delta,
                            const float* __restrict__ cand,
                            const float* __restrict__ h0,
                            const float* __restrict__ r_h,
                            float* __restrict__ h_all,
                            unsigned short* __restrict__ hhi,
                            unsigned short* __restrict__ hlo,
                            int T, int BD, int D)
{
    int lane = blockIdx.x * blockDim.x + threadIdx.x;
    if (lane >= BD) return;

    float h = h0[lane];
    float rh = r_h[lane % D];
    h_all[lane] = h;

    const float* dp = delta + lane;
    const float* cp = cand + lane;
    float* hp = h_all + BD + lane;
    unsigned short* hip = hhi + lane;
    unsigned short* lop = hlo + lane;

    const int U = 8;
    int nG = T / U;
    float db[2][U], cb[2][U];
#pragma unroll
    for (int u = 0; u < U; ++u) {
        db[0][u] = dp[(size_t)u * BD];
        cb[0][u] = cp[(size_t)u * BD];
    }
    int buf = 0;
    for (int g = 0; g < nG; ++g) {
        int nbuf = buf ^ 1;
        if (g + 1 < nG) {
            size_t base = (size_t)(g + 1) * U * BD;
#pragma unroll
            for (int u = 0; u < U; ++u) {
                db[nbuf][u] = dp[base + (size_t)u * BD];
                cb[nbuf][u] = cp[base + (size_t)u * BD];
            }
        }
        size_t ob = (size_t)g * U * BD;
#pragma unroll
        for (int u = 0; u < U; ++u) {
            float d = db[buf][u], c = cb[buf][u];
            float cv = tanhf(fmaf(rh, h, c));
            h = fmaf(d, cv - h, h);
            size_t idx = ob + (size_t)u * BD;
            hp[idx] = h;
            uint32_t bits = __float_as_uint(h);
            hip[idx] = (unsigned short)(bits >> 16);
            float res = h - __uint_as_float(bits & 0xFFFF0000u);
            uint32_t pl;
            asm("cvt.rn.bf16x2.f32 %0, %1, %1;" : "=r"(pl) : "f"(res));
            lop[idx] = (unsigned short)(pl & 0xffff);
        }
        buf = nbuf;
    }
}

// ---------------------------------------------------------------------------
extern "C" void kernel_launch(void* const* d_in, const int* in_sizes, int n_in,
                              void* d_out, int out_size)
{
    const float* x       = (const float*)d_in[0];
    const float* h0      = (const float*)d_in[1];
    const float* W_x     = (const float*)d_in[2];
    const float* r_h     = (const float*)d_in[3];
    const float* b       = (const float*)d_in[4];
    const float* W_delta = (const float*)d_in[5];
    const float* b_delta = (const float*)d_in[6];
    const float* W_out   = (const float*)d_in[7];
    float* out = (float*)d_out;

    int D  = (int)(sqrt((double)in_sizes[2]) + 0.5);
    int Bn = in_sizes[1] / D;
    int Tn = in_sizes[0] / (Bn * D);
    int BD = Bn * D;
    int M  = Tn * Bn;

    float *gd, *gc, *ghall;
    unsigned short *xs_hi, *xs_lo, *h_hi, *h_lo, *w01_hi, *w01_lo, *wo_hi, *wo_lo;
    cudaGetSymbolAddress((void**)&gd,     g_delta);
    cudaGetSymbolAddress((void**)&gc,     g_cand);
    cudaGetSymbolAddress((void**)&ghall,  g_hall);
    cudaGetSymbolAddress((void**)&xs_hi,  g_xs_hi);
    cudaGetSymbolAddress((void**)&xs_lo,  g_xs_lo);
    cudaGetSymbolAddress((void**)&h_hi,   g_h_hi);
    cudaGetSymbolAddress((void**)&h_lo,   g_h_lo);
    cudaGetSymbolAddress((void**)&w01_hi, g_w01_hi);
    cudaGetSymbolAddress((void**)&w01_lo, g_w01_lo);
    cudaGetSymbolAddress((void**)&wo_hi,  g_wo_hi);
    cudaGetSymbolAddress((void**)&wo_lo,  g_wo_lo);

    float *hall, *outs;
    long need_both = (long)(Tn + 1) * BD + (long)M * D;
    if ((long)out_size >= need_both) {
        hall = out;
        outs = out + (size_t)(Tn + 1) * BD;
    } else {
        hall = ghall;
        outs = out;
    }

    cudaFuncSetAttribute(gemm_tc<0>, cudaFuncAttributeMaxDynamicSharedMemorySize, GSMEM);
    cudaFuncSetAttribute(gemm_tc<1>, cudaFuncAttributeMaxDynamicSharedMemorySize, GSMEM);

    // Phase 0: pre-split inputs/weights to bf16 hi/lo
    int n4x = (M * D) / 4;
    int n4w = (D * D) / 4;
    split_kernel<<<(n4x + 255) / 256, 256>>>(x, xs_hi, xs_lo, n4x);
    split_kernel<<<(n4w + 255) / 256, 256>>>(W_delta, w01_hi,         w01_lo,         n4w);
    split_kernel<<<(n4w + 255) / 256, 256>>>(W_x,     w01_hi + D * D, w01_lo + D * D, n4w);
    split_kernel<<<(n4w + 255) / 256, 256>>>(W_out,   wo_hi,          wo_lo,          n4w);

    // Phase 1: fused delta|cand GEMM (N = 2D)
    gemm_tc<0><<<dim3(2 * D / 256, M / 128), 256, GSMEM>>>(
        xs_hi, xs_lo, w01_hi, w01_lo, b_delta, b, gd, gc, nullptr, D, D);

    // Phase 2: diagonal scan (+ bf16 split of h for the out-GEMM)
    scan_kernel<<<(BD + 127) / 128, 128>>>(gd, gc, h0, r_h, hall, h_hi, h_lo, Tn, BD, D);

    // Phase 3: output GEMM with fused compete-softmax + silu epilogue
    gemm_tc<1><<<dim3(D / 256, M / 128), 256, GSMEM>>>(
        h_hi, h_lo, wo_hi, wo_lo, nullptr, nullptr, outs, nullptr, hall + BD, D, D);
}